// round 17
// baseline (speedup 1.0000x reference)
#include <cuda_runtime.h>
#include <cuda_bf16.h>
#include <cstdint>

// Problem constants
#define S_LEN   4096
#define K_CH    4
#define NCHAR   (S_LEN * K_CH)      // 16384 char steps
#define A_SZ    25
#define EC      64
#define HR      256
#define DL      128
#define EW      128
#define HW      512
#define ZR      (4 * HR)            // 1024
#define ZW      (4 * HW)            // 2048
#define WBLK    64                  // CTAs for the word recurrence (8 units each)

#define SENT 0xFFFFFFFFu            // negative NaN; finite h never encodes it

// ---------------- scratch (static __device__ — no allocations) ----------------
__device__ float d_zalpha[A_SZ * ZR];          // per-letter char input projection (+b_r)
__device__ float d_hword[S_LEN * HR];          // char-LSTM h at word boundaries only
__device__ float d_xw[S_LEN * ZW];             // word-LSTM input projections (+b_w)
__device__ int   d_flg_w[WBLK * 32];           // word per-CTA monotonic step flags

// ---------------- helpers ----------------
__device__ __forceinline__ float tanh_a(float x) {
    float r; asm("tanh.approx.f32 %0, %1;" : "=f"(r) : "f"(x)); return r;
}
__device__ __forceinline__ float sigm(float x) {
    return fmaf(tanh_a(0.5f * x), 0.5f, 0.5f);
}
__device__ __forceinline__ uint32_t smem_u32(const void* p) {
    uint32_t a;
    asm("{ .reg .u64 t; cvta.to.shared.u64 t, %1; cvt.u32.u64 %0, t; }" : "=r"(a) : "l"(p));
    return a;
}
__device__ __forceinline__ uint32_t mapa_rank(uint32_t laddr, uint32_t rank) {
    uint32_t r;
    asm("mapa.shared::cluster.u32 %0, %1, %2;" : "=r"(r) : "r"(laddr), "r"(rank));
    return r;
}
__device__ __forceinline__ void st_cluster_f32(uint32_t raddr, float v) {
    asm volatile("st.shared::cluster.f32 [%0], %1;" :: "r"(raddr), "f"(v) : "memory");
}
__device__ __forceinline__ uint32_t my_cluster_rank() {
    uint32_t r; asm("mov.u32 %0, %%cluster_ctarank;" : "=r"(r)); return r;
}
__device__ __forceinline__ void wait_flag_lane(volatile int* f, int t) {
    int guard = 0;
    while (*f < t) { if (++guard > (1 << 16)) break; }
}
// ---- packed fp32x2 math (Blackwell FFMA2) ----
__device__ __forceinline__ unsigned long long pk2(float lo, float hi) {
    unsigned long long r;
    asm("mov.b64 %0, {%1,%2};" : "=l"(r) : "f"(lo), "f"(hi));
    return r;
}
__device__ __forceinline__ void fma2(unsigned long long& d,
                                     unsigned long long a, unsigned long long b) {
    asm("fma.rn.f32x2 %0, %1, %2, %0;" : "+l"(d) : "l"(a), "l"(b));
}
__device__ __forceinline__ float upk_sum(unsigned long long v) {
    float lo, hi;
    asm("mov.b64 {%0,%1}, %2;" : "=f"(lo), "=f"(hi) : "l"(v));
    return lo + hi;
}

// ---------------- K-1: zero the word flag array ----------------
__global__ void k_fill() {
    for (int i = threadIdx.x; i < WBLK * 32; i += blockDim.x) d_flg_w[i] = 0;
}

// ---------------- K0: Z_alpha = E_char @ W_ih_r^T + b_r  [25 x 1024] ----------------
__global__ void k_zalpha(const float* __restrict__ E_char,
                         const float* __restrict__ W_ih_r,
                         const float* __restrict__ b_r) {
    __shared__ float es[EC];
    int a = blockIdx.x;
    if (threadIdx.x < EC) es[threadIdx.x] = E_char[a * EC + threadIdx.x];
    __syncthreads();
    for (int r = threadIdx.x; r < ZR; r += blockDim.x) {
        float acc = b_r[r];
        const float* wr = W_ih_r + r * EC;
        #pragma unroll 16
        for (int e = 0; e < EC; e++) acc += wr[e] * es[e];
        d_zalpha[a * ZR + r] = acc;
    }
}

// ---------------- K1a: char-LSTM — 16-CTA cluster (non-portable), half per-lane work -
// CTA rank owns units [16r,16r+16); warp u owns units j = 16r + 2u + m (2/warp).
// lane = m*16 + q*4 + s4: each lane does 64 MAC = 32 FFMA2; 2 shfl_xor reduce.
// Transport: proven 4-slot value-sentinel DSMEM push, 1 bar/step; unit's 16 lanes
// push its h to the 16 ranks (one scalar st.cluster each).
__global__ void __launch_bounds__(256, 1)
k_char16(const float* __restrict__ W_hh, const int* __restrict__ cid) {
    __shared__ __align__(16) float hbuf[4][HR];
    const int tid  = threadIdx.x;
    const int u    = tid >> 5;
    const int lane = tid & 31;
    const int m    = lane >> 4;                   // unit within warp (0..1)
    const int q    = (lane >> 2) & 3;             // gate (i,f,g,o)
    const int s4   = lane & 3;                    // dot slice (0..3)
    const uint32_t rank = my_cluster_rank();
    const int j    = (int)rank * 16 + u * 2 + m;
    const int row  = q * HR + j;

    // packed per-lane weights: pairs of W_row[s4*4 + kk*16 + e], 64 floats
    unsigned long long w2[32];
    #pragma unroll
    for (int kk = 0; kk < 16; kk++) {
        float4 v = *(const float4*)(W_hh + (size_t)row * HR + s4 * 4 + kk * 16);
        w2[kk*2+0] = pk2(v.x, v.y);
        w2[kk*2+1] = pk2(v.z, v.w);
    }

    #pragma unroll
    for (int s = 0; s < 4; s++) ((uint32_t*)hbuf)[s * HR + tid] = SENT;
    __syncthreads();
    asm volatile("barrier.cluster.arrive.aligned;" ::: "memory");
    asm volatile("barrier.cluster.wait.aligned;"   ::: "memory");

    const uint32_t hb_base = smem_u32(hbuf);
    float cst = 0.0f;

    for (int t = 0; t < NCHAR; t++) {
        float xv = __ldg(d_zalpha + __ldg(cid + t) * ZR + row);
        float acc = 0.0f;
        if (t > 0) {
            const int ps = (t - 1) & 3;
            {   // poll own word of the previous-step slot (local SMEM, volatile)
                volatile uint32_t* p = (volatile uint32_t*)&hbuf[ps][0] + tid;
                int g = 0;
                while (*p == SENT) { if (++g > (1 << 16)) break; }
            }
            __syncthreads();                        // the ONLY bar per step
            if (t >= 2)
                ((uint32_t*)&hbuf[(t - 2) & 3][0])[tid] = SENT;
            unsigned long long a01 = 0ull, a23 = 0ull;
            #pragma unroll
            for (int kk = 0; kk < 16; kk++) {
                ulonglong2 hv = *(const ulonglong2*)(&hbuf[ps][s4 * 4 + kk * 16]);
                fma2(a01, w2[kk*2+0], hv.x);
                fma2(a23, w2[kk*2+1], hv.y);
            }
            acc = upk_sum(a01) + upk_sum(a23);
        }
        if (s4 == 0) acc += xv;                     // xv summed once per (unit,gate)
        acc += __shfl_xor_sync(0xffffffffu, acc, 1);
        acc += __shfl_xor_sync(0xffffffffu, acc, 2); // all 4 slices -> full z
        float act = (q == 2) ? tanh_a(acc) : sigm(acc);
        const int base = lane & 16;                  // m*16
        float ai = __shfl_sync(0xffffffffu, act, base + 0);
        float af = __shfl_sync(0xffffffffu, act, base + 4);
        float ag = __shfl_sync(0xffffffffu, act, base + 8);
        float ao = __shfl_sync(0xffffffffu, act, base + 12);
        cst = af * cst + ai * ag;                    // redundant per-unit, consistent
        float h = ao * tanh_a(cst);                  // all 16 lanes of unit hold h
        {   // lane (m, lane&15) pushes unit j's h to rank lane&15, slot t&3
            uint32_t laddr = hb_base + (uint32_t)(((t & 3) * HR + j) * 4);
            st_cluster_f32(mapa_rank(laddr, (uint32_t)(lane & 15)), h);
        }
        if ((t & 3) == 3 && (lane & 15) == 0)
            d_hword[(size_t)(t >> 2) * HR + j] = h;
    }
    asm volatile("barrier.cluster.arrive.aligned;" ::: "memory");
    asm volatile("barrier.cluster.wait.aligned;"   ::: "memory");
}

// ---------------- K1b: fallback — R16-proven 8-CTA char kernel (unchanged) ----------
__global__ void __launch_bounds__(256, 1) __cluster_dims__(8, 1, 1)
k_char8(const float* __restrict__ W_hh, const int* __restrict__ cid) {
    __shared__ __align__(16) float hbuf[4][HR];
    const int tid  = threadIdx.x;
    const int u    = tid >> 5;
    const int lane = tid & 31;
    const int m    = lane >> 3;
    const int q    = (lane >> 1) & 3;
    const int s2   = lane & 1;
    const uint32_t rank = my_cluster_rank();
    const int jb   = (int)rank * 32 + u * 4;
    const int j    = jb + m;
    const int row  = q * HR + j;

    unsigned long long w2[64];
    #pragma unroll
    for (int kk = 0; kk < 32; kk++) {
        float4 v = *(const float4*)(W_hh + (size_t)row * HR + s2 * 4 + kk * 8);
        w2[kk*2+0] = pk2(v.x, v.y);
        w2[kk*2+1] = pk2(v.z, v.w);
    }
    #pragma unroll
    for (int s = 0; s < 4; s++) ((uint32_t*)hbuf)[s * HR + tid] = SENT;
    __syncthreads();
    asm volatile("barrier.cluster.arrive.aligned;" ::: "memory");
    asm volatile("barrier.cluster.wait.aligned;"   ::: "memory");

    const uint32_t hb_base = smem_u32(hbuf);
    float cst = 0.0f;
    for (int t = 0; t < NCHAR; t++) {
        float xv = __ldg(d_zalpha + __ldg(cid + t) * ZR + row);
        float acc = 0.0f;
        if (t > 0) {
            const int ps = (t - 1) & 3;
            {
                volatile uint32_t* p = (volatile uint32_t*)&hbuf[ps][0] + tid;
                int g = 0;
                while (*p == SENT) { if (++g > (1 << 16)) break; }
            }
            __syncthreads();
            if (t >= 2)
                ((uint32_t*)&hbuf[(t - 2) & 3][0])[tid] = SENT;
            unsigned long long a01 = 0ull, a23 = 0ull;
            #pragma unroll
            for (int kk = 0; kk < 32; kk++) {
                ulonglong2 hv = *(const ulonglong2*)(&hbuf[ps][s2 * 4 + kk * 8]);
                fma2(a01, w2[kk*2+0], hv.x);
                fma2(a23, w2[kk*2+1], hv.y);
            }
            acc = upk_sum(a01) + upk_sum(a23);
        }
        if (s2 == 0) acc += xv;
        acc += __shfl_xor_sync(0xffffffffu, acc, 1);
        float act = (q == 2) ? tanh_a(acc) : sigm(acc);
        const int base = lane & 24;
        float ai = __shfl_sync(0xffffffffu, act, base + 0);
        float af = __shfl_sync(0xffffffffu, act, base + 2);
        float ag = __shfl_sync(0xffffffffu, act, base + 4);
        float ao = __shfl_sync(0xffffffffu, act, base + 6);
        cst = af * cst + ai * ag;
        float h = ao * tanh_a(cst);
        {
            uint32_t laddr = hb_base + (uint32_t)(((t & 3) * HR + j) * 4);
            st_cluster_f32(mapa_rank(laddr, (uint32_t)(lane & 7)), h);
        }
        if ((t & 3) == 3 && (lane & 7) == 0)
            d_hword[(size_t)(t >> 2) * HR + j] = h;
    }
    asm volatile("barrier.cluster.arrive.aligned;" ::: "memory");
    asm volatile("barrier.cluster.wait.aligned;"   ::: "memory");
}

// ---------------- K2: latent + word input projections ----------------
__global__ void __launch_bounds__(256)
k_wordin(const float* __restrict__ W_lat, const float* __restrict__ b_lat,
         const float* __restrict__ E_word, const float* __restrict__ W_ih_w,
         const float* __restrict__ b_w,   const int* __restrict__ word_ids) {
    __shared__ float hw[16 * HR];          // 16 KB
    __shared__ float us[16 * (EW + DL)];   // 16 KB
    const int tid = threadIdx.x;
    const int s0  = blockIdx.x * 16;

    #pragma unroll
    for (int i = 0; i < 16; i++)
        hw[i * HR + tid] = d_hword[(size_t)(s0 + i) * HR + tid];
    for (int idx = tid; idx < 16 * EW; idx += 256) {
        int si = idx >> 7, e = idx & 127;
        us[si * 256 + e] = __ldg(E_word + (size_t)__ldg(word_ids + s0 + si) * EW + e);
    }
    __syncthreads();

    for (int idx = tid; idx < 16 * DL; idx += 256) {
        int si = idx >> 7, d = idx & 127;
        float acc = b_lat[d];
        const float* wr = W_lat + d * HR;
        #pragma unroll 8
        for (int l = 0; l < HR; l++) acc += __ldg(wr + l) * hw[si * HR + l];
        us[si * 256 + 128 + d] = tanhf(acc);
    }
    __syncthreads();

    for (int rr = 0; rr < 8; rr++) {
        int r = tid + rr * 256;
        const float* wr = W_ih_w + (size_t)r * 256;
        float bb = b_w[r];
        float acc[16];
        #pragma unroll
        for (int si = 0; si < 16; si++) acc[si] = bb;
        for (int c = 0; c < 256; c++) {
            float wv = __ldg(wr + c);
            #pragma unroll
            for (int si = 0; si < 16; si++) acc[si] += wv * us[si * 256 + c];
        }
        #pragma unroll
        for (int si = 0; si < 16; si++) d_xw[(size_t)(s0 + si) * ZW + r] = acc[si];
    }
}

// ---------------- K3: word-LSTM — 64 CTAs x 256 thr, merged poll+load (R16-proven) ---
__global__ void __launch_bounds__(256, 1)
k_word(const float* __restrict__ W_hh, float* __restrict__ out) {
    __shared__ __align__(16) float hs[HW];
    const int tid  = threadIdx.x;
    const int u    = tid >> 5;
    const int lane = tid & 31;
    const int q    = lane >> 3;
    const int s8   = lane & 7;
    const int j    = blockIdx.x * 8 + u;
    const int row  = q * HW + j;

    unsigned long long w2[32];
    #pragma unroll
    for (int kk = 0; kk < 16; kk++) {
        float4 v = *(const float4*)(W_hh + (size_t)row * HW + s8 * 4 + kk * 32);
        w2[kk*2+0] = pk2(v.x, v.y);
        w2[kk*2+1] = pk2(v.z, v.w);
    }

    float cst = 0.0f;
    for (int t = 0; t < S_LEN; t++) {
        float xv = 0.0f;
        if (s8 == 0) xv = __ldg(d_xw + (size_t)t * ZW + row);
        float acc = 0.0f;
        if (t > 0) {
            if (tid < HW / 4) {
                wait_flag_lane((volatile int*)&d_flg_w[(tid >> 1) * 32], t);
                float4 v = __ldcg((const float4*)(out + (size_t)(t - 1) * HW) + tid);
                ((float4*)hs)[tid] = v;
            }
            __syncthreads();
            unsigned long long a01 = 0ull, a23 = 0ull;
            #pragma unroll
            for (int kk = 0; kk < 16; kk++) {
                ulonglong2 hv = *(const ulonglong2*)(&hs[s8 * 4 + kk * 32]);
                fma2(a01, w2[kk*2+0], hv.x);
                fma2(a23, w2[kk*2+1], hv.y);
            }
            acc = upk_sum(a01) + upk_sum(a23);
        }
        if (s8 == 0) acc += xv;
        acc += __shfl_xor_sync(0xffffffffu, acc, 4);
        acc += __shfl_xor_sync(0xffffffffu, acc, 2);
        acc += __shfl_xor_sync(0xffffffffu, acc, 1);
        float act = (q == 2) ? tanh_a(acc) : sigm(acc);
        float ai = __shfl_sync(0xffffffffu, act, 0);
        float af = __shfl_sync(0xffffffffu, act, 8);
        float ag = __shfl_sync(0xffffffffu, act, 16);
        float ao = __shfl_sync(0xffffffffu, act, 24);
        cst = af * cst + ai * ag;
        float h = ao * tanh_a(cst);
        if (lane == 0) __stcg(out + (size_t)t * HW + j, h);
        __syncthreads();
        if (tid == 0) {
            __threadfence();
            *(volatile int*)&d_flg_w[blockIdx.x * 32] = t + 1;
        }
    }
}

// ---------------- launch ----------------
extern "C" void kernel_launch(void* const* d_in, const int* in_sizes, int n_in,
                              void* d_out, int out_size) {
    const float* E_char  = (const float*)d_in[0];
    const float* W_ih_r  = (const float*)d_in[1];
    const float* W_hh_r  = (const float*)d_in[2];
    const float* b_r     = (const float*)d_in[3];
    const float* W_lat   = (const float*)d_in[4];
    const float* b_lat   = (const float*)d_in[5];
    const float* E_word  = (const float*)d_in[6];
    const float* W_ih_w  = (const float*)d_in[7];
    const float* W_hh_w  = (const float*)d_in[8];
    const float* b_w     = (const float*)d_in[9];
    const int*   word_ids = (const int*)d_in[10];
    const int*   char_ids = (const int*)d_in[11];
    float* out = (float*)d_out;

    k_fill<<<1, 1024>>>();
    k_zalpha<<<A_SZ, 256>>>(E_char, W_ih_r, b_r);

    // char recurrence: try the 16-CTA non-portable cluster; fall back to proven 8-CTA.
    cudaFuncSetAttribute(k_char16, cudaFuncAttributeNonPortableClusterSizeAllowed, 1);
    cudaLaunchConfig_t cfg = {};
    cfg.gridDim  = dim3(16, 1, 1);
    cfg.blockDim = dim3(256, 1, 1);
    cfg.dynamicSmemBytes = 0;
    cfg.stream = 0;
    cudaLaunchAttribute attrs[1];
    attrs[0].id = cudaLaunchAttributeClusterDimension;
    attrs[0].val.clusterDim.x = 16;
    attrs[0].val.clusterDim.y = 1;
    attrs[0].val.clusterDim.z = 1;
    cfg.attrs = attrs;
    cfg.numAttrs = 1;
    cudaError_t e = cudaLaunchKernelEx(&cfg, k_char16, W_hh_r, char_ids);
    if (e != cudaSuccess) {
        cudaGetLastError();                       // clear sticky error
        k_char8<<<8, 256>>>(W_hh_r, char_ids);    // R16-proven fallback
    }

    k_wordin<<<S_LEN / 16, 256>>>(W_lat, b_lat, E_word, W_ih_w, b_w, word_ids);
    k_word<<<WBLK, 256>>>(W_hh_w, out);
}